// round 4
// baseline (speedup 1.0000x reference)
#include <cuda_runtime.h>
#include <cstdint>

// Problem constants (match reference)
#define NU 100000
#define NI 50000
#define NN 150000          // NU + NI
#define DD 64
#define TT 8
#define HEADS 4

// ---------------------------------------------------------------------------
// Device-global scratch (no allocation allowed in kernel_launch)
// ---------------------------------------------------------------------------
__device__ float g_P[32 * 64];      // P[i=h*8+t][j] : score projection (scaled by 1/4)
__device__ float g_C[8 * 32];       // C[t0][i]      : qoff·koff score constants (scaled)
__device__ float g_WvWo[64 * 64];   // Wv @ Wo
__device__ float g_VoffO[32 * 64];  // per (h,t): (voff[t] head-h slice) @ Wo
__device__ int   g_ei64;            // edge_index is int64?
__device__ int   g_ti64;            // time_indices is int64?

__device__ float g_X[(size_t)NN * DD];    // x after temporal attention
__device__ float g_H0[(size_t)NN * DD];   // x + 0.5*causal
__device__ float g_H1[(size_t)NN * DD];   // after layer 0
__device__ float g_AGG[(size_t)NN * DD];  // segment-sum accumulator (reused)

// ---------------------------------------------------------------------------
// Kernel 1: tiny precompute (1 block). Builds P, C, WvWo, VoffO and detects
// index dtypes.
// ---------------------------------------------------------------------------
__global__ void precompute_kernel(
    const float* __restrict__ te,
    const float* __restrict__ Wq, const float* __restrict__ bq,
    const float* __restrict__ Wk, const float* __restrict__ bk,
    const float* __restrict__ Wv, const float* __restrict__ bv,
    const float* __restrict__ Wo,
    const void* __restrict__ ei_raw, const void* __restrict__ ti_raw)
{
    __shared__ float qoff[8 * 64], koff[8 * 64], voff[8 * 64];
    int tid = threadIdx.x;

    for (int idx = tid; idx < 8 * 64; idx += blockDim.x) {
        int t = idx >> 6, d = idx & 63;
        float q = bq[d], k = bk[d], v = bv[d];
        for (int j = 0; j < 64; j++) {
            float x = te[t * 64 + j];
            q += x * Wq[j * 64 + d];
            k += x * Wk[j * 64 + d];
            v += x * Wv[j * 64 + d];
        }
        qoff[idx] = q; koff[idx] = k; voff[idx] = v;
    }
    __syncthreads();

    // P and VoffO : 32x64 each
    for (int idx = tid; idx < 32 * 64; idx += blockDim.x) {
        int i = idx >> 6, j = idx & 63;
        int h = i >> 3, t = i & 7;
        float s = 0.f;
        #pragma unroll
        for (int m = 0; m < 16; m++)
            s += Wq[j * 64 + h * 16 + m] * koff[t * 64 + h * 16 + m];
        g_P[idx] = 0.25f * s;  // 1/sqrt(16)

        float s2 = 0.f;
        #pragma unroll
        for (int m = 0; m < 16; m++)
            s2 += voff[t * 64 + h * 16 + m] * Wo[(h * 16 + m) * 64 + j];
        g_VoffO[idx] = s2;
    }
    // C : 8x32
    for (int idx = tid; idx < 8 * 32; idx += blockDim.x) {
        int t0 = idx >> 5, i = idx & 31;
        int h = i >> 3, t = i & 7;
        float s = 0.f;
        #pragma unroll
        for (int m = 0; m < 16; m++)
            s += qoff[t0 * 64 + h * 16 + m] * koff[t * 64 + h * 16 + m];
        g_C[idx] = 0.25f * s;
    }
    // WvWo : 64x64
    for (int idx = tid; idx < 64 * 64; idx += blockDim.x) {
        int k = idx >> 6, j = idx & 63;
        float s = 0.f;
        for (int d = 0; d < 64; d++) s += Wv[k * 64 + d] * Wo[d * 64 + j];
        g_WvWo[idx] = s;
    }

    if (tid == 0) {
        // Detect int64 vs int32: if int64 (values < 2^31), every odd 32-bit
        // word is 0. If int32, odd words are random node-ids / time-ids.
        const int* e32 = (const int*)ei_raw;
        const int* t32 = (const int*)ti_raw;
        int is64 = 1;
        for (int i = 0; i < 64; i++) if (e32[2 * i + 1] != 0) { is64 = 0; break; }
        g_ei64 = is64;
        is64 = 1;
        for (int i = 0; i < 64; i++) if (t32[2 * i + 1] != 0) { is64 = 0; break; }
        g_ti64 = is64;
    }
}

// ---------------------------------------------------------------------------
// Kernel 2: zero the aggregation buffer
// ---------------------------------------------------------------------------
__global__ void zero_agg_kernel()
{
    size_t i = (size_t)blockIdx.x * blockDim.x + threadIdx.x;
    float4* p = (float4*)g_AGG;
    if (i < (size_t)NN * DD / 4) p[i] = make_float4(0.f, 0.f, 0.f, 0.f);
}

// ---------------------------------------------------------------------------
// Kernel 3: per-node temporal attention (collapsed MHA).
// Block = 256 threads = 8 warps; each warp handles 4 nodes per tile.
// Writes g_X (x after attention) and g_H0 (x + 0.5*causal).
// ---------------------------------------------------------------------------
__device__ __forceinline__ float softmax8(float s)
{
    const unsigned FULL = 0xffffffffu;
    float m = fmaxf(s, __shfl_xor_sync(FULL, s, 1));
    m = fmaxf(m, __shfl_xor_sync(FULL, m, 2));
    m = fmaxf(m, __shfl_xor_sync(FULL, m, 4));
    float e = __expf(s - m);
    float t = e + __shfl_xor_sync(FULL, e, 1);
    t += __shfl_xor_sync(FULL, t, 2);
    t += __shfl_xor_sync(FULL, t, 4);
    return e / t;
}

__global__ void __launch_bounds__(256) node_kernel(
    const float* __restrict__ user_emb,
    const float* __restrict__ item_emb,
    const void* __restrict__ ti_raw,
    const float* __restrict__ te,
    const float* __restrict__ bo,
    const float* __restrict__ causal,
    int numTiles)
{
    __shared__ float sP[32 * 65];     // padded against bank conflicts
    __shared__ float sW[64 * 64];     // WvWo
    __shared__ float sVO[32 * 64];
    __shared__ float sC[256];
    __shared__ float sTE[8 * 64];
    __shared__ float sBO[64];
    __shared__ float sX[8][4][64];

    int tid = threadIdx.x;
    for (int idx = tid; idx < 32 * 64; idx += 256) {
        sP[(idx >> 6) * 65 + (idx & 63)] = g_P[idx];
        sVO[idx] = g_VoffO[idx];
    }
    for (int idx = tid; idx < 64 * 64; idx += 256) sW[idx] = g_WvWo[idx];
    if (tid < 256) sC[tid] = g_C[tid];
    for (int idx = tid; idx < 512; idx += 256) sTE[idx] = te[idx];
    if (tid < 64) sBO[tid] = bo[tid];
    int ti64 = g_ti64;
    __syncthreads();

    int w = tid >> 5, lane = tid & 31;
    const long long* tp64 = (const long long*)ti_raw;
    const int*       tp32 = (const int*)ti_raw;
    const unsigned FULL = 0xffffffffu;

    float* x0 = &sX[w][0][0];
    float* x1 = &sX[w][1][0];
    float* x2 = &sX[w][2][0];
    float* x3 = &sX[w][3][0];

    for (int tile = blockIdx.x; tile < numTiles; tile += gridDim.x) {
        int base = tile * 32 + w * 4;
        int t0a = 0, t0b = 0, t0c = 0, t0d = 0;

        // Stage x for the 4 nodes into shared
        #pragma unroll
        for (int m = 0; m < 4; m++) {
            int n = base + m;
            float2 xv = make_float2(0.f, 0.f);
            int tt = 0;
            if (n < NN) {
                const float* src = (n < NU) ? (user_emb + (size_t)n * 64)
                                            : (item_emb + (size_t)(n - NU) * 64);
                xv = ((const float2*)src)[lane];
                tt = ti64 ? (int)tp64[n] : tp32[n];
            }
            sX[w][m][2 * lane]     = xv.x;
            sX[w][m][2 * lane + 1] = xv.y;
            if (m == 0) t0a = tt; else if (m == 1) t0b = tt;
            else if (m == 2) t0c = tt; else t0d = tt;
        }
        __syncwarp();

        // Scores: lane = combo i = h*8+t
        float s0 = 0.f, s1 = 0.f, s2 = 0.f, s3 = 0.f;
        const float* pr = sP + lane * 65;
        #pragma unroll 8
        for (int j = 0; j < 64; j++) {
            float p = pr[j];
            s0 += p * x0[j]; s1 += p * x1[j];
            s2 += p * x2[j]; s3 += p * x3[j];
        }
        s0 += sC[t0a * 32 + lane];
        s1 += sC[t0b * 32 + lane];
        s2 += sC[t0c * 32 + lane];
        s3 += sC[t0d * 32 + lane];

        float a0 = softmax8(s0);
        float a1 = softmax8(s1);
        float a2 = softmax8(s2);
        float a3 = softmax8(s3);

        // Output accumulators: lane owns dims (2*lane, 2*lane+1)
        float bx = sBO[2 * lane], by = sBO[2 * lane + 1];
        float2 acc0, acc1, acc2, acc3;
        acc0.x = bx + sTE[t0a * 64 + 2 * lane]     + x0[2 * lane];
        acc0.y = by + sTE[t0a * 64 + 2 * lane + 1] + x0[2 * lane + 1];
        acc1.x = bx + sTE[t0b * 64 + 2 * lane]     + x1[2 * lane];
        acc1.y = by + sTE[t0b * 64 + 2 * lane + 1] + x1[2 * lane + 1];
        acc2.x = bx + sTE[t0c * 64 + 2 * lane]     + x2[2 * lane];
        acc2.y = by + sTE[t0c * 64 + 2 * lane + 1] + x2[2 * lane + 1];
        acc3.x = bx + sTE[t0d * 64 + 2 * lane]     + x3[2 * lane];
        acc3.y = by + sTE[t0d * 64 + 2 * lane + 1] + x3[2 * lane + 1];

        // attn-weighted VoffO contribution
        #pragma unroll 8
        for (int i = 0; i < 32; i++) {
            float2 v = *(const float2*)(sVO + i * 64 + 2 * lane);
            float b0 = __shfl_sync(FULL, a0, i);
            float b1 = __shfl_sync(FULL, a1, i);
            float b2 = __shfl_sync(FULL, a2, i);
            float b3 = __shfl_sync(FULL, a3, i);
            acc0.x += b0 * v.x; acc0.y += b0 * v.y;
            acc1.x += b1 * v.x; acc1.y += b1 * v.y;
            acc2.x += b2 * v.x; acc2.y += b2 * v.y;
            acc3.x += b3 * v.x; acc3.y += b3 * v.y;
        }

        // x @ WvWo
        #pragma unroll 8
        for (int k = 0; k < 64; k++) {
            float2 v = *(const float2*)(sW + k * 64 + 2 * lane);
            float h0 = x0[k], h1 = x1[k], h2 = x2[k], h3 = x3[k];
            acc0.x += h0 * v.x; acc0.y += h0 * v.y;
            acc1.x += h1 * v.x; acc1.y += h1 * v.y;
            acc2.x += h2 * v.x; acc2.y += h2 * v.y;
            acc3.x += h3 * v.x; acc3.y += h3 * v.y;
        }

        // Store X and H0
        #pragma unroll
        for (int m = 0; m < 4; m++) {
            int n = base + m;
            if (n >= NN) continue;
            float2 r = (m == 0) ? acc0 : (m == 1) ? acc1 : (m == 2) ? acc2 : acc3;
            float2 c = ((const float2*)(causal + (size_t)n * 64))[lane];
            ((float2*)(g_X + (size_t)n * 64))[lane] = r;
            float2 h;
            h.x = r.x + 0.5f * c.x;
            h.y = r.y + 0.5f * c.y;
            ((float2*)(g_H0 + (size_t)n * 64))[lane] = h;
        }
        __syncwarp();
    }
}

// ---------------------------------------------------------------------------
// Kernel 4: edge scatter (segment_sum). 16 lanes per edge, red.v4.f32.
// mode 0: gather from g_H0;  mode 1: gather from g_H1.
// ---------------------------------------------------------------------------
__global__ void __launch_bounds__(256) scatter_kernel(
    const void* __restrict__ ei_raw, int E, int mode)
{
    const float* __restrict__ H = mode ? g_H1 : g_H0;
    int gw = (int)((blockIdx.x * (unsigned)blockDim.x + threadIdx.x) >> 5);
    int lane = threadIdx.x & 31;
    int half = lane >> 4, sub = lane & 15;
    long long e = (long long)gw * 2 + half;
    bool valid = (e < (long long)E);
    long long ec = valid ? e : 0;

    long long src, dst;
    if (g_ei64) {
        const long long* p = (const long long*)ei_raw;
        src = p[ec];
        dst = p[(size_t)E + ec];
    } else {
        const int* p = (const int*)ei_raw;
        src = p[ec];
        dst = p[(size_t)E + ec];
    }
    if (valid) {
        float4 v = *((const float4*)(H + (size_t)src * 64) + sub);
        float* dp = g_AGG + (size_t)dst * 64 + sub * 4;
        asm volatile("red.global.add.v4.f32 [%0], {%1,%2,%3,%4};"
                     :: "l"(dp), "f"(v.x), "f"(v.y), "f"(v.z), "f"(v.w)
                     : "memory");
    }
}

// ---------------------------------------------------------------------------
// Kernel 5: dense GNN layer.  h_out = relu(h_in@Ws + agg@Wn + b)
// mode 0: in = g_H0 -> out = g_H1
// mode 1: in = g_H1 -> all = g_X + relu(...), written to d_out (x2 if dup)
// Block = 256 (8 warps), each warp handles 2 nodes per tile.
// ---------------------------------------------------------------------------
__global__ void __launch_bounds__(256) dense_kernel(
    const float* __restrict__ Ws, const float* __restrict__ Wn,
    const float* __restrict__ bb,
    float* __restrict__ out, int dup, int numTiles, int mode)
{
    __shared__ float sWs[64 * 64];
    __shared__ float sWn[64 * 64];
    __shared__ float sB[64];
    __shared__ float sV[8][2][128];   // [h(64) | agg(64)] per node

    int tid = threadIdx.x;
    for (int idx = tid; idx < 64 * 64; idx += 256) {
        sWs[idx] = Ws[idx];
        sWn[idx] = Wn[idx];
    }
    if (tid < 64) sB[tid] = bb[tid];
    __syncthreads();

    int w = tid >> 5, lane = tid & 31;
    const float* __restrict__ Hin = mode ? g_H1 : g_H0;

    for (int tile = blockIdx.x; tile < numTiles; tile += gridDim.x) {
        int base = tile * 16 + w * 2;

        #pragma unroll
        for (int m = 0; m < 2; m++) {
            int n = base + m;
            float2 h = make_float2(0.f, 0.f), a = make_float2(0.f, 0.f);
            if (n < NN) {
                h = ((const float2*)(Hin + (size_t)n * 64))[lane];
                a = ((const float2*)(g_AGG + (size_t)n * 64))[lane];
            }
            sV[w][m][2 * lane]       = h.x;
            sV[w][m][2 * lane + 1]   = h.y;
            sV[w][m][64 + 2 * lane]     = a.x;
            sV[w][m][64 + 2 * lane + 1] = a.y;
        }
        __syncwarp();

        float2 acc0, acc1;
        acc0.x = acc1.x = sB[2 * lane];
        acc0.y = acc1.y = sB[2 * lane + 1];

        const float* v0 = &sV[w][0][0];
        const float* v1 = &sV[w][1][0];
        #pragma unroll 8
        for (int k = 0; k < 64; k++) {
            float2 ws = *(const float2*)(sWs + k * 64 + 2 * lane);
            float2 wn = *(const float2*)(sWn + k * 64 + 2 * lane);
            float h0 = v0[k], a0 = v0[64 + k];
            float h1 = v1[k], a1 = v1[64 + k];
            acc0.x += h0 * ws.x + a0 * wn.x;
            acc0.y += h0 * ws.y + a0 * wn.y;
            acc1.x += h1 * ws.x + a1 * wn.x;
            acc1.y += h1 * ws.y + a1 * wn.y;
        }

        #pragma unroll
        for (int m = 0; m < 2; m++) {
            int n = base + m;
            if (n >= NN) continue;
            float2 acc = (m == 0) ? acc0 : acc1;
            float rx = fmaxf(acc.x, 0.f);
            float ry = fmaxf(acc.y, 0.f);
            if (mode == 0) {
                float2 r = make_float2(rx, ry);
                ((float2*)(g_H1 + (size_t)n * 64))[lane] = r;
            } else {
                float2 xv = ((const float2*)(g_X + (size_t)n * 64))[lane];
                float2 r = make_float2(xv.x + rx, xv.y + ry);
                ((float2*)(out + (size_t)n * 64))[lane] = r;
                if (dup)
                    ((float2*)(out + (size_t)(NN + n) * 64))[lane] = r;
            }
        }
        __syncwarp();
    }
}

// ---------------------------------------------------------------------------
// kernel_launch
// Inputs (metadata order):
//  0 edge_index (int, 2*E)   1 edge_timestamps (f32, E)   2 time_indices (int, N)
//  3 user_emb  4 item_emb  5 temporal_emb  6 causal_emb
//  7 Wq 8 bq 9 Wk 10 bk 11 Wv 12 bv 13 Wo 14 bo
//  15 W_self_0 16 W_neigh_0 17 b_0   18 W_self_1 19 W_neigh_1 20 b_1
// Output: concat(all_embeddings, user_embeddings, item_embeddings) = [all | all]
// ---------------------------------------------------------------------------
extern "C" void kernel_launch(void* const* d_in, const int* in_sizes, int n_in,
                              void* d_out, int out_size)
{
    const void*  ei     = d_in[0];
    const void*  ti     = d_in[2];
    const float* user   = (const float*)d_in[3];
    const float* item   = (const float*)d_in[4];
    const float* te     = (const float*)d_in[5];
    const float* causal = (const float*)d_in[6];
    const float* Wq = (const float*)d_in[7],  *bq = (const float*)d_in[8];
    const float* Wk = (const float*)d_in[9],  *bk = (const float*)d_in[10];
    const float* Wv = (const float*)d_in[11], *bv = (const float*)d_in[12];
    const float* Wo = (const float*)d_in[13], *bo = (const float*)d_in[14];
    const float* Ws0 = (const float*)d_in[15], *Wn0 = (const float*)d_in[16];
    const float* b0  = (const float*)d_in[17];
    const float* Ws1 = (const float*)d_in[18], *Wn1 = (const float*)d_in[19];
    const float* b1  = (const float*)d_in[20];

    int E = in_sizes[1];                       // edge_timestamps element count
    float* out = (float*)d_out;
    int dup = (out_size >= 2 * NN * DD) ? 1 : 0;

    int nodeTiles  = (NN + 31) / 32;
    int denseTiles = (NN + 15) / 16;
    int zeroBlocks = (NN * DD / 4 + 255) / 256;
    int scatBlocks = (E + 15) / 16;

    precompute_kernel<<<1, 256>>>(te, Wq, bq, Wk, bk, Wv, bv, Wo, ei, ti);
    zero_agg_kernel<<<zeroBlocks, 256>>>();
    node_kernel<<<1184, 256>>>(user, item, ti, te, bo, causal, nodeTiles);
    scatter_kernel<<<scatBlocks, 256>>>(ei, E, 0);
    dense_kernel<<<1184, 256>>>(Ws0, Wn0, b0, nullptr, 0, denseTiles, 0);
    zero_agg_kernel<<<zeroBlocks, 256>>>();
    scatter_kernel<<<scatBlocks, 256>>>(ei, E, 1);
    dense_kernel<<<1184, 256>>>(Ws1, Wn1, b1, out, dup, denseTiles, 1);
}